// round 9
// baseline (speedup 1.0000x reference)
#include <cuda_runtime.h>
#include <cuda_fp16.h>
#include <cstdint>

#define BATCH 4
#define SEQ   2048
#define DIM   1024
#define MQ    (BATCH * SEQ)   // 8192

// ---------------------------------------------------------------------------
// Persistent scratch (device globals — allocation-free per harness rules)
// ---------------------------------------------------------------------------
__device__ half  g_xh[(long)MQ * DIM];
__device__ half  g_Wh[3][(long)DIM * DIM];
__device__ half  g_QKV[3][(long)MQ * DIM];        // Q, K, V contiguous slices
__device__ float g_S[(long)BATCH * SEQ * SEQ];
__device__ half  g_Ph[(long)BATCH * SEQ * SEQ];

// ---------------------------------------------------------------------------
// helpers
// ---------------------------------------------------------------------------
__device__ __forceinline__ uint32_t smem_u32(const void* p) {
    uint32_t a;
    asm("{ .reg .u64 t; cvta.to.shared.u64 t, %1; cvt.u32.u64 %0, t; }" : "=r"(a) : "l"(p));
    return a;
}
__device__ __forceinline__ void cp8(uint32_t dst, const void* src) {
    asm volatile("cp.async.ca.shared.global [%0], [%1], 8;" :: "r"(dst), "l"(src));
}
__device__ __forceinline__ void cp_commit() {
    asm volatile("cp.async.commit_group;" ::: "memory");
}
__device__ __forceinline__ void cp_wait1() {
    asm volatile("cp.async.wait_group 1;" ::: "memory");
}
__device__ __forceinline__ void ldsm4(uint32_t r[4], uint32_t addr) {
    asm volatile("ldmatrix.sync.aligned.m8n8.x4.shared.b16 {%0,%1,%2,%3}, [%4];"
                 : "=r"(r[0]), "=r"(r[1]), "=r"(r[2]), "=r"(r[3]) : "r"(addr));
}
__device__ __forceinline__ void ldsm4t(uint32_t r[4], uint32_t addr) {
    asm volatile("ldmatrix.sync.aligned.m8n8.x4.trans.shared.b16 {%0,%1,%2,%3}, [%4];"
                 : "=r"(r[0]), "=r"(r[1]), "=r"(r[2]), "=r"(r[3]) : "r"(addr));
}
// f16-accumulator MMA: D,C are 2 b32 regs = 4 halves
__device__ __forceinline__ void mma16816_h(uint32_t d[2], const uint32_t a[4],
                                           uint32_t b0, uint32_t b1) {
    asm volatile(
        "mma.sync.aligned.m16n8k16.row.col.f16.f16.f16.f16 "
        "{%0,%1}, {%2,%3,%4,%5}, {%6,%7}, {%0,%1};"
        : "+r"(d[0]), "+r"(d[1])
        : "r"(a[0]), "r"(a[1]), "r"(a[2]), "r"(a[3]), "r"(b0), "r"(b1));
}

// ---------------------------------------------------------------------------
// fp32 -> fp16 casts: y=0 -> x, y=1..3 -> Wq/Wk/Wv
// ---------------------------------------------------------------------------
__global__ void cast_all(const float* __restrict__ x,
                         const float* __restrict__ w0, const float* __restrict__ w1,
                         const float* __restrict__ w2,
                         half* __restrict__ xh, half* __restrict__ Wh)
{
    const int y = blockIdx.y;
    const float* s;
    half* d;
    int n4;
    if (y == 0) { s = x;  d = xh; n4 = MQ * DIM / 4; }
    else {
        s = (y == 1) ? w0 : (y == 2) ? w1 : w2;
        d = Wh + (long)(y - 1) * DIM * DIM;
        n4 = DIM * DIM / 4;
    }
    int i = blockIdx.x * blockDim.x + threadIdx.x;
    if (i >= n4) return;
    float4 v = ((const float4*)s)[i];
    half2 a; a.x = __float2half(v.x); a.y = __float2half(v.y);
    half2 b; b.x = __float2half(v.z); b.y = __float2half(v.w);
    ((half2*)d)[2 * i] = a;
    ((half2*)d)[2 * i + 1] = b;
}

// ---------------------------------------------------------------------------
// fp16 HMMA GEMM: f16 accumulation per 32-K slab, fp32 master accumulators.
// Register-lean: warp tile processed in two nf-groups (c16 = 16 regs).
//   C[M,N] = A[M,K] * op(B)
//   BKMAJOR=1: B is [N,K] row-major (NT).   BKMAJOR=0: B is [K,N] row-major (NN).
//   MODE 1 (projection): z selects W slice / bias / output slice; fp16 out + bias.
//   MODE 2: fp32 out * alpha; z = batch index.
// CTA tile 128x128, BK=32, 8 warps (2x4), warp tile 64x32.
// ---------------------------------------------------------------------------
#define LDA    40    // elems; 80B rows (bank-conflict-free for ldmatrix)
#define LDBNN  136   // elems; 272B rows
#define STAGES 3

#define A_TILE_B   (128 * LDA * 2)          // 10240
#define BNT_TILE_B (128 * LDA * 2)          // 10240
#define BNN_TILE_B (32 * LDBNN * 2)         // 8704

template <bool BKMAJOR, int MODE>
__global__ __launch_bounds__(256, 2)
void hmma_gemm(const half* __restrict__ A, const half* __restrict__ B,
               const float* __restrict__ b0, const float* __restrict__ b1,
               const float* __restrict__ b2,
               float* __restrict__ Cf, half* __restrict__ Ch,
               int M, int N, int K, long sA, long sB, long sC, float alpha)
{
    constexpr int B_TILE_B = BKMAJOR ? BNT_TILE_B : BNN_TILE_B;
    constexpr int OFF_B    = A_TILE_B;
    constexpr int STAGE_B  = A_TILE_B + B_TILE_B;

    extern __shared__ char smem[];
    const uint32_t sb = smem_u32(smem);

    const int tid = threadIdx.x;
    const int lane = tid & 31;
    const int wid = tid >> 5;
    const int wm = wid >> 2;        // 0..1
    const int wn = wid & 3;         // 0..3

    const int bz = blockIdx.z;
    const float* bias = b0;
    if (MODE == 1) {
        B += bz * sB;
        Ch += bz * sC;
        bias = (bz == 0) ? b0 : (bz == 1) ? b1 : b2;
    } else {
        A += bz * sA;
        B += bz * sB;
    }
    const int m0 = blockIdx.y * 128;
    const int n0 = blockIdx.x * 128;

    float c[4][4][4];
    #pragma unroll
    for (int i = 0; i < 4; i++)
        #pragma unroll
        for (int j = 0; j < 4; j++)
            #pragma unroll
            for (int r = 0; r < 4; r++) c[i][j][r] = 0.f;

    // ---- async copy of one 32-K slab into stage st ----
    auto issue_stage = [&](int st, int k0) {
        const uint32_t s0 = sb + st * STAGE_B;
        #pragma unroll
        for (int i = 0; i < 4; i++) {
            const int q = i * 256 + tid;
            const int r = q >> 3, ch = q & 7;
            cp8(s0 + r * 80 + ch * 8, A + (long)(m0 + r) * K + k0 + ch * 4);
        }
        if (BKMAJOR) {
            #pragma unroll
            for (int i = 0; i < 4; i++) {
                const int q = i * 256 + tid;
                const int r = q >> 3, ch = q & 7;
                cp8(s0 + OFF_B + r * 80 + ch * 8, B + (long)(n0 + r) * K + k0 + ch * 4);
            }
        } else {
            #pragma unroll
            for (int i = 0; i < 4; i++) {
                const int q = i * 256 + tid;
                const int r = q >> 5, ch = q & 31;
                cp8(s0 + OFF_B + r * 272 + ch * 8, B + (long)(k0 + r) * N + n0 + ch * 4);
            }
        }
        cp_commit();
    };

    const int NIT = K >> 5;
    issue_stage(0, 0);
    issue_stage(1, 32);

    int st = 0;
    for (int it = 0; it < NIT; it++) {
        cp_wait1();
        __syncthreads();
        if (it + 2 < NIT) issue_stage((st + 2) % STAGES, (it + 2) * 32);

        const half* tA = (const half*)(smem + st * STAGE_B);
        const half* tB = (const half*)(smem + st * STAGE_B + OFF_B);

        // two nf-groups of 16 columns each; f16 slab accumulators per group
        #pragma unroll
        for (int g = 0; g < 2; g++) {
            uint32_t c16[4][2][2];
            #pragma unroll
            for (int mf = 0; mf < 4; mf++) {
                c16[mf][0][0] = c16[mf][0][1] = 0u;
                c16[mf][1][0] = c16[mf][1][1] = 0u;
            }

            #pragma unroll
            for (int ks = 0; ks < 2; ks++) {
                const int kk = ks * 16;
                uint32_t fb[4];
                if (BKMAJOR) {
                    const int row = wn * 32 + g * 16 + (lane & 15);
                    const int col = kk + (lane >> 4) * 8;
                    ldsm4(fb, smem_u32(&tB[row * LDA + col]));
                } else {
                    const int row = kk + (lane >> 4) * 8 + (lane & 7);
                    const int col = wn * 32 + g * 16 + ((lane >> 3) & 1) * 8;
                    ldsm4t(fb, smem_u32(&tB[row * LDBNN + col]));
                }
                #pragma unroll
                for (int mf = 0; mf < 4; mf++) {
                    uint32_t fa[4];
                    const int row = wm * 64 + mf * 16 + (lane & 15);
                    const int col = kk + (lane >> 4) * 8;
                    ldsm4(fa, smem_u32(&tA[row * LDA + col]));
                    mma16816_h(c16[mf][0], fa, fb[0], fb[2]);
                    mma16816_h(c16[mf][1], fa, fb[1], fb[3]);
                }
            }

            // promote slab sums into fp32 master accumulators
            #pragma unroll
            for (int mf = 0; mf < 4; mf++)
                #pragma unroll
                for (int j = 0; j < 2; j++) {
                    const int nf = g * 2 + j;
                    float2 lo = __half22float2(*(__half2*)&c16[mf][j][0]);
                    float2 hi = __half22float2(*(__half2*)&c16[mf][j][1]);
                    c[mf][nf][0] += lo.x;  c[mf][nf][1] += lo.y;
                    c[mf][nf][2] += hi.x;  c[mf][nf][3] += hi.y;
                }
        }
        st = (st + 1) % STAGES;
    }

    // ---- epilogue ----
    #pragma unroll
    for (int mf = 0; mf < 4; mf++) {
        const int m_lo = m0 + wm * 64 + mf * 16 + (lane >> 2);
        #pragma unroll
        for (int nf = 0; nf < 4; nf++) {
            const int n = n0 + wn * 32 + nf * 8 + (lane & 3) * 2;
            if (MODE == 1) {
                const float v0 = bias[n], v1 = bias[n + 1];
                __half2 h0; h0.x = __float2half(c[mf][nf][0] + v0);
                h0.y = __float2half(c[mf][nf][1] + v1);
                __half2 h1; h1.x = __float2half(c[mf][nf][2] + v0);
                h1.y = __float2half(c[mf][nf][3] + v1);
                *(__half2*)(Ch + (long)m_lo * N + n) = h0;
                *(__half2*)(Ch + (long)(m_lo + 8) * N + n) = h1;
            } else {
                float* co = Cf + bz * sC;
                float2 v0 = make_float2(c[mf][nf][0] * alpha, c[mf][nf][1] * alpha);
                float2 v1 = make_float2(c[mf][nf][2] * alpha, c[mf][nf][3] * alpha);
                *(float2*)(co + (long)m_lo * N + n) = v0;
                *(float2*)(co + (long)(m_lo + 8) * N + n) = v1;
            }
        }
    }
}

// ---------------------------------------------------------------------------
// Softmax over rows of g_S (len SEQ) -> fp16 probs
// ---------------------------------------------------------------------------
__global__ __launch_bounds__(256)
void softmax_rows(const float* __restrict__ S, half* __restrict__ Ph)
{
    const float* p = S + (long)blockIdx.x * SEQ;
    half* ph = Ph + (long)blockIdx.x * SEQ;
    const int tid = threadIdx.x;
    __shared__ float red[8];

    float v[8];
    #pragma unroll
    for (int i = 0; i < 8; i++) v[i] = p[tid + i * 256];

    float m = v[0];
    #pragma unroll
    for (int i = 1; i < 8; i++) m = fmaxf(m, v[i]);
    #pragma unroll
    for (int o = 16; o; o >>= 1) m = fmaxf(m, __shfl_xor_sync(0xffffffffu, m, o));
    if ((tid & 31) == 0) red[tid >> 5] = m;
    __syncthreads();
    m = red[0];
    #pragma unroll
    for (int w = 1; w < 8; w++) m = fmaxf(m, red[w]);
    __syncthreads();

    float s = 0.f;
    #pragma unroll
    for (int i = 0; i < 8; i++) { v[i] = __expf(v[i] - m); s += v[i]; }
    #pragma unroll
    for (int o = 16; o; o >>= 1) s += __shfl_xor_sync(0xffffffffu, s, o);
    if ((tid & 31) == 0) red[tid >> 5] = s;
    __syncthreads();
    s = 0.f;
    #pragma unroll
    for (int w = 0; w < 8; w++) s += red[w];
    const float inv = 1.f / s;

    #pragma unroll
    for (int i = 0; i < 8; i++)
        ph[tid + i * 256] = __float2half(v[i] * inv);
}

// ---------------------------------------------------------------------------
// Launch
// ---------------------------------------------------------------------------
extern "C" void kernel_launch(void* const* d_in, const int* in_sizes, int n_in,
                              void* d_out, int out_size)
{
    const float* x  = (const float*)d_in[0];
    const float* Wq = (const float*)d_in[1];
    const float* bq = (const float*)d_in[2];
    const float* Wk = (const float*)d_in[3];
    const float* bk = (const float*)d_in[4];
    const float* Wv = (const float*)d_in[5];
    const float* bv = (const float*)d_in[6];
    float* out = (float*)d_out;

    half *xh, *Wh, *QKV, *Ph;
    float* S;
    cudaGetSymbolAddress((void**)&xh, g_xh);
    cudaGetSymbolAddress((void**)&Wh, g_Wh);
    cudaGetSymbolAddress((void**)&QKV, g_QKV);
    cudaGetSymbolAddress((void**)&S, g_S);
    cudaGetSymbolAddress((void**)&Ph, g_Ph);

    half* Qh = QKV;
    half* Kh = QKV + (long)MQ * DIM;
    half* Vh = QKV + 2L * MQ * DIM;

    const int SMEM_NT = STAGES * (A_TILE_B + BNT_TILE_B);   // 61440
    const int SMEM_NN = STAGES * (A_TILE_B + BNN_TILE_B);   // 56832
    cudaFuncSetAttribute(hmma_gemm<true, 1>, cudaFuncAttributeMaxDynamicSharedMemorySize, SMEM_NT);
    cudaFuncSetAttribute(hmma_gemm<true, 2>, cudaFuncAttributeMaxDynamicSharedMemorySize, SMEM_NT);
    cudaFuncSetAttribute(hmma_gemm<false, 2>, cudaFuncAttributeMaxDynamicSharedMemorySize, SMEM_NN);

    const long WSZ = (long)DIM * DIM;

    // 1) casts: x + all three W in one launch
    {
        dim3 grid((MQ * DIM / 4 + 255) / 256, 4, 1);
        cast_all<<<grid, 256>>>(x, Wq, Wk, Wv, xh, Wh);
    }

    // 2) projections: ONE launch, grid.z selects Q/K/V   (NT, fp16 out)
    {
        dim3 grid(DIM / 128, MQ / 128, 3), blk(256);
        hmma_gemm<true, 1><<<grid, blk, SMEM_NT>>>(xh, Wh, bq, bk, bv,
                                                   nullptr, QKV, MQ, DIM, DIM,
                                                   0, WSZ, (long)MQ * DIM, 1.f);
    }

    // 3) scores: S = (1/32) Q K^T  per batch  (NT, fp32 out)
    {
        dim3 grid(SEQ / 128, SEQ / 128, BATCH), blk(256);
        hmma_gemm<true, 2><<<grid, blk, SMEM_NT>>>(Qh, Kh, nullptr, nullptr, nullptr,
                                                   S, nullptr, SEQ, SEQ, DIM,
                                                   (long)SEQ * DIM, (long)SEQ * DIM, (long)SEQ * SEQ,
                                                   0.03125f);
    }

    // 4) softmax -> P fp16
    softmax_rows<<<BATCH * SEQ, 256>>>(S, Ph);

    // 5) out = P @ V  per batch  (NN via ldmatrix.trans, fp32 out)
    {
        dim3 grid(DIM / 128, SEQ / 128, BATCH), blk(256);
        hmma_gemm<false, 2><<<grid, blk, SMEM_NN>>>(Ph, Vh, nullptr, nullptr, nullptr,
                                                    out, nullptr, SEQ, DIM, SEQ,
                                                    (long)SEQ * SEQ, (long)SEQ * DIM, (long)SEQ * DIM,
                                                    1.f);
    }
}

// round 10
// speedup vs baseline: 1.2548x; 1.2548x over previous
#include <cuda_runtime.h>
#include <cuda_fp16.h>
#include <cstdint>

#define BATCH 4
#define SEQ   2048
#define DIM   1024
#define MQ    (BATCH * SEQ)   // 8192

// ---------------------------------------------------------------------------
// Persistent scratch (device globals — allocation-free per harness rules)
// ---------------------------------------------------------------------------
__device__ half  g_xh[(long)MQ * DIM];
__device__ half  g_Wh[3][(long)DIM * DIM];
__device__ half  g_QKV[3][(long)MQ * DIM];        // Q, K, V contiguous slices
__device__ float g_S[(long)BATCH * SEQ * SEQ];
__device__ half  g_Ph[(long)BATCH * SEQ * SEQ];

// ---------------------------------------------------------------------------
// helpers
// ---------------------------------------------------------------------------
__device__ __forceinline__ uint32_t smem_u32(const void* p) {
    uint32_t a;
    asm("{ .reg .u64 t; cvta.to.shared.u64 t, %1; cvt.u32.u64 %0, t; }" : "=r"(a) : "l"(p));
    return a;
}
__device__ __forceinline__ void cp8(uint32_t dst, const void* src) {
    asm volatile("cp.async.ca.shared.global [%0], [%1], 8;" :: "r"(dst), "l"(src));
}
__device__ __forceinline__ void cp_commit() {
    asm volatile("cp.async.commit_group;" ::: "memory");
}
__device__ __forceinline__ void cp_wait1() {
    asm volatile("cp.async.wait_group 1;" ::: "memory");
}
__device__ __forceinline__ void ldsm4(uint32_t r[4], uint32_t addr) {
    asm volatile("ldmatrix.sync.aligned.m8n8.x4.shared.b16 {%0,%1,%2,%3}, [%4];"
                 : "=r"(r[0]), "=r"(r[1]), "=r"(r[2]), "=r"(r[3]) : "r"(addr));
}
__device__ __forceinline__ void ldsm4t(uint32_t r[4], uint32_t addr) {
    asm volatile("ldmatrix.sync.aligned.m8n8.x4.trans.shared.b16 {%0,%1,%2,%3}, [%4];"
                 : "=r"(r[0]), "=r"(r[1]), "=r"(r[2]), "=r"(r[3]) : "r"(addr));
}
__device__ __forceinline__ void mma16816(float c[4], const uint32_t a[4],
                                         uint32_t b0, uint32_t b1) {
    asm volatile(
        "mma.sync.aligned.m16n8k16.row.col.f32.f16.f16.f32 "
        "{%0,%1,%2,%3}, {%4,%5,%6,%7}, {%8,%9}, {%0,%1,%2,%3};"
        : "+f"(c[0]), "+f"(c[1]), "+f"(c[2]), "+f"(c[3])
        : "r"(a[0]), "r"(a[1]), "r"(a[2]), "r"(a[3]), "r"(b0), "r"(b1));
}

// ---------------------------------------------------------------------------
// fp32 -> fp16 casts: y=0 -> x, y=1..3 -> Wq/Wk/Wv
// ---------------------------------------------------------------------------
__global__ void cast_all(const float* __restrict__ x,
                         const float* __restrict__ w0, const float* __restrict__ w1,
                         const float* __restrict__ w2,
                         half* __restrict__ xh, half* __restrict__ Wh)
{
    const int y = blockIdx.y;
    const float* s;
    half* d;
    int n4;
    if (y == 0) { s = x;  d = xh; n4 = MQ * DIM / 4; }
    else {
        s = (y == 1) ? w0 : (y == 2) ? w1 : w2;
        d = Wh + (long)(y - 1) * DIM * DIM;
        n4 = DIM * DIM / 4;
    }
    int i = blockIdx.x * blockDim.x + threadIdx.x;
    if (i >= n4) return;
    float4 v = ((const float4*)s)[i];
    half2 a; a.x = __float2half(v.x); a.y = __float2half(v.y);
    half2 b; b.x = __float2half(v.z); b.y = __float2half(v.w);
    ((half2*)d)[2 * i] = a;
    ((half2*)d)[2 * i + 1] = b;
}

// ---------------------------------------------------------------------------
// fp16 HMMA GEMM (f32 accum), cp.async 3-stage pipeline.
//   C[M,N] = A[M,K] * op(B)
//   BKMAJOR=1: B is [N,K] row-major (NT).   BKMAJOR=0: B is [K,N] row-major (NN).
//   MODE 1 (projection): z selects W slice / bias / output slice; A shared.
//          fp16 out + bias.
//   MODE 2: fp32 out * alpha; z = batch index (strides sA/sB/sC).
// CTA tile 128x128, BK=32, 8 warps (2x4), warp tile 64x32.
// ---------------------------------------------------------------------------
#define LDA    40    // elems; 80B rows (bank-conflict-free for ldmatrix)
#define LDBNN  136   // elems; 272B rows
#define STAGES 3

#define A_TILE_B   (128 * LDA * 2)          // 10240
#define BNT_TILE_B (128 * LDA * 2)          // 10240
#define BNN_TILE_B (32 * LDBNN * 2)         // 8704

template <bool BKMAJOR, int MODE>
__global__ __launch_bounds__(256)
void hmma_gemm(const half* __restrict__ A, const half* __restrict__ B,
               const float* __restrict__ b0, const float* __restrict__ b1,
               const float* __restrict__ b2,
               float* __restrict__ Cf, half* __restrict__ Ch,
               int M, int N, int K, long sA, long sB, long sC, float alpha)
{
    constexpr int B_TILE_B = BKMAJOR ? BNT_TILE_B : BNN_TILE_B;
    constexpr int OFF_B    = A_TILE_B;
    constexpr int STAGE_B  = A_TILE_B + B_TILE_B;

    extern __shared__ char smem[];
    const uint32_t sb = smem_u32(smem);

    const int tid = threadIdx.x;
    const int lane = tid & 31;
    const int wid = tid >> 5;
    const int wm = wid >> 2;        // 0..1
    const int wn = wid & 3;         // 0..3

    const int bz = blockIdx.z;
    const float* bias = b0;
    if (MODE == 1) {
        B += bz * sB;
        Ch += bz * sC;
        bias = (bz == 0) ? b0 : (bz == 1) ? b1 : b2;
    } else {
        A += bz * sA;
        B += bz * sB;
    }
    const int m0 = blockIdx.y * 128;
    const int n0 = blockIdx.x * 128;

    float c[4][4][4];
    #pragma unroll
    for (int i = 0; i < 4; i++)
        #pragma unroll
        for (int j = 0; j < 4; j++)
            #pragma unroll
            for (int r = 0; r < 4; r++) c[i][j][r] = 0.f;

    // ---- async copy of one 32-K slab into stage st ----
    auto issue_stage = [&](int st, int k0) {
        const uint32_t s0 = sb + st * STAGE_B;
        #pragma unroll
        for (int i = 0; i < 4; i++) {
            const int q = i * 256 + tid;
            const int r = q >> 3, ch = q & 7;
            cp8(s0 + r * 80 + ch * 8, A + (long)(m0 + r) * K + k0 + ch * 4);
        }
        if (BKMAJOR) {
            #pragma unroll
            for (int i = 0; i < 4; i++) {
                const int q = i * 256 + tid;
                const int r = q >> 3, ch = q & 7;
                cp8(s0 + OFF_B + r * 80 + ch * 8, B + (long)(n0 + r) * K + k0 + ch * 4);
            }
        } else {
            #pragma unroll
            for (int i = 0; i < 4; i++) {
                const int q = i * 256 + tid;
                const int r = q >> 5, ch = q & 31;
                cp8(s0 + OFF_B + r * 272 + ch * 8, B + (long)(k0 + r) * N + n0 + ch * 4);
            }
        }
        cp_commit();
    };

    const int NIT = K >> 5;
    issue_stage(0, 0);
    issue_stage(1, 32);

    int st = 0;
    for (int it = 0; it < NIT; it++) {
        cp_wait1();
        __syncthreads();
        if (it + 2 < NIT) issue_stage((st + 2) % STAGES, (it + 2) * 32);

        const half* tA = (const half*)(smem + st * STAGE_B);
        const half* tB = (const half*)(smem + st * STAGE_B + OFF_B);

        #pragma unroll
        for (int ks = 0; ks < 2; ks++) {
            const int kk = ks * 16;
            uint32_t fa[4][4], fb[2][4];
            #pragma unroll
            for (int mf = 0; mf < 4; mf++) {
                const int row = wm * 64 + mf * 16 + (lane & 15);
                const int col = kk + (lane >> 4) * 8;
                ldsm4(fa[mf], smem_u32(&tA[row * LDA + col]));
            }
            if (BKMAJOR) {
                #pragma unroll
                for (int q = 0; q < 2; q++) {
                    const int row = wn * 32 + q * 16 + (lane & 15);
                    const int col = kk + (lane >> 4) * 8;
                    ldsm4(fb[q], smem_u32(&tB[row * LDA + col]));
                }
            } else {
                #pragma unroll
                for (int q = 0; q < 2; q++) {
                    const int row = kk + (lane >> 4) * 8 + (lane & 7);
                    const int col = wn * 32 + q * 16 + ((lane >> 3) & 1) * 8;
                    ldsm4t(fb[q], smem_u32(&tB[row * LDBNN + col]));
                }
            }
            #pragma unroll
            for (int mf = 0; mf < 4; mf++)
                #pragma unroll
                for (int nf = 0; nf < 4; nf++) {
                    const int q = nf >> 1, g = nf & 1;
                    mma16816(c[mf][nf], fa[mf], fb[q][g], fb[q][g + 2]);
                }
        }
        st = (st + 1) % STAGES;
    }

    // ---- epilogue ----
    #pragma unroll
    for (int mf = 0; mf < 4; mf++) {
        const int m_lo = m0 + wm * 64 + mf * 16 + (lane >> 2);
        #pragma unroll
        for (int nf = 0; nf < 4; nf++) {
            const int n = n0 + wn * 32 + nf * 8 + (lane & 3) * 2;
            if (MODE == 1) {
                const float v0 = bias[n], v1 = bias[n + 1];
                __half2 h0; h0.x = __float2half(c[mf][nf][0] + v0);
                h0.y = __float2half(c[mf][nf][1] + v1);
                __half2 h1; h1.x = __float2half(c[mf][nf][2] + v0);
                h1.y = __float2half(c[mf][nf][3] + v1);
                *(__half2*)(Ch + (long)m_lo * N + n) = h0;
                *(__half2*)(Ch + (long)(m_lo + 8) * N + n) = h1;
            } else {
                float* co = Cf + bz * sC;
                float2 v0 = make_float2(c[mf][nf][0] * alpha, c[mf][nf][1] * alpha);
                float2 v1 = make_float2(c[mf][nf][2] * alpha, c[mf][nf][3] * alpha);
                *(float2*)(co + (long)m_lo * N + n) = v0;
                *(float2*)(co + (long)(m_lo + 8) * N + n) = v1;
            }
        }
    }
}

// ---------------------------------------------------------------------------
// Softmax over rows of g_S (len SEQ) -> fp16 probs.  Vectorized:
// float4 loads (2/thread), packed 4xhalf stores (uint2), per-row block.
// ---------------------------------------------------------------------------
__global__ __launch_bounds__(256)
void softmax_rows(const float* __restrict__ S, half* __restrict__ Ph)
{
    const float4* p4 = (const float4*)(S + (long)blockIdx.x * SEQ);
    half* ph = Ph + (long)blockIdx.x * SEQ;
    const int tid = threadIdx.x;
    __shared__ float red[8];

    float4 v0 = p4[tid];
    float4 v1 = p4[tid + 256];

    float m = fmaxf(fmaxf(fmaxf(v0.x, v0.y), fmaxf(v0.z, v0.w)),
                    fmaxf(fmaxf(v1.x, v1.y), fmaxf(v1.z, v1.w)));
    #pragma unroll
    for (int o = 16; o; o >>= 1) m = fmaxf(m, __shfl_xor_sync(0xffffffffu, m, o));
    if ((tid & 31) == 0) red[tid >> 5] = m;
    __syncthreads();
    m = red[0];
    #pragma unroll
    for (int w = 1; w < 8; w++) m = fmaxf(m, red[w]);
    __syncthreads();

    v0.x = __expf(v0.x - m); v0.y = __expf(v0.y - m);
    v0.z = __expf(v0.z - m); v0.w = __expf(v0.w - m);
    v1.x = __expf(v1.x - m); v1.y = __expf(v1.y - m);
    v1.z = __expf(v1.z - m); v1.w = __expf(v1.w - m);
    float s = (v0.x + v0.y) + (v0.z + v0.w) + (v1.x + v1.y) + (v1.z + v1.w);
    #pragma unroll
    for (int o = 16; o; o >>= 1) s += __shfl_xor_sync(0xffffffffu, s, o);
    if ((tid & 31) == 0) red[tid >> 5] = s;
    __syncthreads();
    s = 0.f;
    #pragma unroll
    for (int w = 0; w < 8; w++) s += red[w];
    const float inv = 1.f / s;

    __half2 a, b;
    uint2 pk;
    a.x = __float2half(v0.x * inv); a.y = __float2half(v0.y * inv);
    b.x = __float2half(v0.z * inv); b.y = __float2half(v0.w * inv);
    pk.x = *(uint32_t*)&a; pk.y = *(uint32_t*)&b;
    ((uint2*)ph)[tid] = pk;
    a.x = __float2half(v1.x * inv); a.y = __float2half(v1.y * inv);
    b.x = __float2half(v1.z * inv); b.y = __float2half(v1.w * inv);
    pk.x = *(uint32_t*)&a; pk.y = *(uint32_t*)&b;
    ((uint2*)ph)[tid + 256] = pk;
}

// ---------------------------------------------------------------------------
// Launch
// ---------------------------------------------------------------------------
extern "C" void kernel_launch(void* const* d_in, const int* in_sizes, int n_in,
                              void* d_out, int out_size)
{
    const float* x  = (const float*)d_in[0];
    const float* Wq = (const float*)d_in[1];
    const float* bq = (const float*)d_in[2];
    const float* Wk = (const float*)d_in[3];
    const float* bk = (const float*)d_in[4];
    const float* Wv = (const float*)d_in[5];
    const float* bv = (const float*)d_in[6];
    float* out = (float*)d_out;

    half *xh, *Wh, *QKV, *Ph;
    float* S;
    cudaGetSymbolAddress((void**)&xh, g_xh);
    cudaGetSymbolAddress((void**)&Wh, g_Wh);
    cudaGetSymbolAddress((void**)&QKV, g_QKV);
    cudaGetSymbolAddress((void**)&S, g_S);
    cudaGetSymbolAddress((void**)&Ph, g_Ph);

    half* Qh = QKV;
    half* Kh = QKV + (long)MQ * DIM;
    half* Vh = QKV + 2L * MQ * DIM;

    const int SMEM_NT = STAGES * (A_TILE_B + BNT_TILE_B);   // 61440
    const int SMEM_NN = STAGES * (A_TILE_B + BNN_TILE_B);   // 56832
    cudaFuncSetAttribute(hmma_gemm<true, 1>, cudaFuncAttributeMaxDynamicSharedMemorySize, SMEM_NT);
    cudaFuncSetAttribute(hmma_gemm<true, 2>, cudaFuncAttributeMaxDynamicSharedMemorySize, SMEM_NT);
    cudaFuncSetAttribute(hmma_gemm<false, 2>, cudaFuncAttributeMaxDynamicSharedMemorySize, SMEM_NN);

    const long WSZ = (long)DIM * DIM;

    // 1) casts: x + all three W in one launch
    {
        dim3 grid((MQ * DIM / 4 + 255) / 256, 4, 1);
        cast_all<<<grid, 256>>>(x, Wq, Wk, Wv, xh, Wh);
    }

    // 2) projections: ONE launch, grid.z selects Q/K/V   (NT, fp16 out)
    {
        dim3 grid(DIM / 128, MQ / 128, 3), blk(256);
        hmma_gemm<true, 1><<<grid, blk, SMEM_NT>>>(xh, Wh, bq, bk, bv,
                                                   nullptr, QKV, MQ, DIM, DIM,
                                                   0, WSZ, (long)MQ * DIM, 1.f);
    }

    // 3) scores: S = (1/32) Q K^T  per batch  (NT, fp32 out)
    {
        dim3 grid(SEQ / 128, SEQ / 128, BATCH), blk(256);
        hmma_gemm<true, 2><<<grid, blk, SMEM_NT>>>(Qh, Kh, nullptr, nullptr, nullptr,
                                                   S, nullptr, SEQ, SEQ, DIM,
                                                   (long)SEQ * DIM, (long)SEQ * DIM, (long)SEQ * SEQ,
                                                   0.03125f);
    }

    // 4) softmax -> P fp16
    softmax_rows<<<BATCH * SEQ, 256>>>(S, Ph);

    // 5) out = P @ V  per batch  (NN via ldmatrix.trans, fp32 out)
    {
        dim3 grid(DIM / 128, SEQ / 128, BATCH), blk(256);
        hmma_gemm<false, 2><<<grid, blk, SMEM_NN>>>(Ph, Vh, nullptr, nullptr, nullptr,
                                                    out, nullptr, SEQ, DIM, SEQ,
                                                    (long)SEQ * SEQ, (long)SEQ * DIM, (long)SEQ * DIM,
                                                    1.f);
    }
}